// round 2
// baseline (speedup 1.0000x reference)
#include <cuda_runtime.h>
#include <cuda_bf16.h>
#include <cstdint>
#include <math.h>

#define TL 2048
#define EMB 256
#define HD 256           // per-direction hidden
#define NT 7
#define TAG_START 5
#define TAG_END 6
#define NEGV -10000.0f

// Scratch (device globals; no allocation allowed)
__device__ float g_gin[2 * TL * 1024];    // [dir][t][1024] x@Wih^T + b_ih + b_hh
__device__ float g_hs[2 * TL * HD];       // [dir][t][HD]
__device__ float g_feats[TL * NT];

// ---------------------------------------------------------------------------
// PTX helpers
// ---------------------------------------------------------------------------
__device__ __forceinline__ uint32_t smem_u32(const void* p) {
    uint32_t a;
    asm("{ .reg .u64 t; cvta.to.shared.u64 t, %1; cvt.u32.u64 %0, t; }" : "=r"(a) : "l"(p));
    return a;
}
__device__ __forceinline__ uint32_t mapa_u32(uint32_t addr, uint32_t rank) {
    uint32_t r;
    asm("mapa.shared::cluster.u32 %0, %1, %2;" : "=r"(r) : "r"(addr), "r"(rank));
    return r;
}
__device__ __forceinline__ void st_cluster_f32(uint32_t addr, float v) {
    asm volatile("st.shared::cluster.u32 [%0], %1;" :: "r"(addr), "r"(__float_as_uint(v)) : "memory");
}
__device__ __forceinline__ void cluster_sync_all() {
    asm volatile("barrier.cluster.arrive.aligned;" ::: "memory");
    asm volatile("barrier.cluster.wait.aligned;" ::: "memory");
}
__device__ __forceinline__ uint32_t my_ctarank() {
    uint32_t r;
    asm("mov.u32 %0, %%cluster_ctarank;" : "=r"(r));
    return r;
}

// ---------------------------------------------------------------------------
// K1: input projection GEMM. Gin[dir][t][row] = X[t]·Wih[row] + bih[row] + bhh[row]
// X[t] = embed[words[t]]. Tile 128(t) x 128(row), k-chunks of 32, 8x8 micro.
// ---------------------------------------------------------------------------
__global__ __launch_bounds__(256) void gin_gemm(
    const int* __restrict__ words, const float* __restrict__ embed,
    const float* __restrict__ Wf, const float* __restrict__ bif, const float* __restrict__ bhf,
    const float* __restrict__ Wb, const float* __restrict__ bib, const float* __restrict__ bhb)
{
    const int dir = blockIdx.z;
    const float* W  = dir ? Wb  : Wf;
    const float* bi = dir ? bib : bif;
    const float* bh = dir ? bhb : bhf;
    const int t0  = blockIdx.x * 128;
    const int r0  = blockIdx.y * 128;

    __shared__ float Xs[128][33];
    __shared__ float Ws[128][33];
    __shared__ int   sw[128];

    const int tid = threadIdx.x;
    const int tx = tid & 15, ty = tid >> 4;   // tx -> row dim (16), ty -> t dim (16)

    if (tid < 128) sw[tid] = words[t0 + tid];

    float acc[8][8];
#pragma unroll
    for (int i = 0; i < 8; i++)
#pragma unroll
        for (int j = 0; j < 8; j++) acc[i][j] = 0.f;

    for (int kb = 0; kb < EMB; kb += 32) {
        __syncthreads();
#pragma unroll
        for (int it = 0; it < 16; it++) {
            int idx = tid + it * 256;          // 0..4095
            int r = idx >> 5, k = idx & 31;
            Xs[r][k] = embed[(size_t)sw[r] * EMB + kb + k];
        }
#pragma unroll
        for (int it = 0; it < 16; it++) {
            int idx = tid + it * 256;
            int r = idx >> 5, k = idx & 31;
            Ws[r][k] = W[(size_t)(r0 + r) * EMB + kb + k];
        }
        __syncthreads();
#pragma unroll
        for (int k = 0; k < 32; k++) {
            float xr[8], wr[8];
#pragma unroll
            for (int i = 0; i < 8; i++) xr[i] = Xs[ty + i * 16][k];
#pragma unroll
            for (int j = 0; j < 8; j++) wr[j] = Ws[tx + j * 16][k];
#pragma unroll
            for (int i = 0; i < 8; i++)
#pragma unroll
                for (int j = 0; j < 8; j++) acc[i][j] = fmaf(xr[i], wr[j], acc[i][j]);
        }
    }
#pragma unroll
    for (int j = 0; j < 8; j++) {
        int row = r0 + tx + j * 16;
        float bb = bi[row] + bh[row];
#pragma unroll
        for (int i = 0; i < 8; i++) {
            int t = t0 + ty + i * 16;
            g_gin[((size_t)dir * TL + t) * 1024 + row] = acc[i][j] + bb;
        }
    }
}

// ---------------------------------------------------------------------------
// K2: sequential BiLSTM. Two 8-CTA clusters (one per direction).
// Each CTA: 32 hidden units = 128 gate rows; Whh slice in registers
// (2 threads/row, 128 weights each as float4). h broadcast via DSMEM stores +
// one cluster barrier per step, double-buffered h.
// ---------------------------------------------------------------------------
__global__ __launch_bounds__(256, 1) __cluster_dims__(8, 1, 1)
void lstm_kernel(const float* __restrict__ Whf, const float* __restrict__ Whb,
                 const float* __restrict__ h0, const float* __restrict__ c0)
{
    __shared__ __align__(16) float hbuf[2 * HD];
    __shared__ float gates[128];

    const int tid = threadIdx.x;
    const int dir = blockIdx.x >> 3;
    const uint32_t crank = my_ctarank();

    const int rowl = tid >> 1;      // 0..127 : gate*32 + u
    const int half = tid & 1;       // which 128-wide half of the k range
    const int gate = rowl >> 5;
    const int u0   = rowl & 31;
    const int grow = gate * 256 + 32 * (int)crank + u0;  // global gate row 0..1023
    const float* Wh = dir ? Whb : Whf;

    // Whh slice -> registers (128 floats as 32 float4)
    float4 w4[32];
    {
        const float4* wp = (const float4*)(Wh + (size_t)grow * HD + (half << 7));
#pragma unroll
        for (int j = 0; j < 32; j++) w4[j] = wp[j];
    }

    // init: h(-1) lives in slot 1 (prev at s=0)
    hbuf[HD + tid] = h0[dir * HD + tid];
    float creg = 0.f;
    if (tid < 32) creg = c0[dir * HD + 32 * (int)crank + tid];

    const uint32_t hloc = smem_u32(hbuf);
    uint32_t peer[8];
#pragma unroll
    for (int r = 0; r < 8; r++) peer[r] = mapa_u32(hloc, (uint32_t)r);

    __syncthreads();
    cluster_sync_all();

    const size_t ginbase = (size_t)dir * TL * 1024 + grow;
    float gin = g_gin[ginbase + (size_t)(dir ? TL - 1 : 0) * 1024];

    for (int s = 0; s < TL; s++) {
        const int prev = (s + 1) & 1;
        const int cur  = s & 1;

        // prefetch next step's input projection (independent of h chain)
        float ginN = 0.f;
        if (s + 1 < TL) {
            int tn = dir ? (TL - 2 - s) : (s + 1);
            ginN = g_gin[ginbase + (size_t)tn * 1024];
        }

        // gate dot: 128 MACs/thread, registers x smem h (broadcast LDS)
        const float4* hp = (const float4*)(hbuf + prev * HD + (half << 7));
        float a0 = 0.f, a1 = 0.f, a2 = 0.f, a3 = 0.f;
#pragma unroll
        for (int j = 0; j < 32; j++) {
            float4 hv = hp[j];
            float4 wv = w4[j];
            a0 = fmaf(wv.x, hv.x, a0);
            a1 = fmaf(wv.y, hv.y, a1);
            a2 = fmaf(wv.z, hv.z, a2);
            a3 = fmaf(wv.w, hv.w, a3);
        }
        float sum = (a0 + a1) + (a2 + a3);
        sum += __shfl_xor_sync(0xffffffffu, sum, 1);
        if (!half) gates[rowl] = sum + gin;
        __syncthreads();

        // activations: warps 0,1,3 sigmoid; warp 2 tanh (uniform per warp)
        if (tid < 128) {
            float v = gates[tid];
            v = (tid >= 64 && tid < 96) ? tanhf(v) : 1.f / (1.f + expf(-v));
            gates[tid] = v;
        }
        __syncthreads();

        if (tid < 32) {
            float gi = gates[tid];
            float gf = gates[32 + tid];
            float gg = gates[64 + tid];
            float go = gates[96 + tid];
            creg = gf * creg + gi * gg;
            float h = go * tanhf(creg);

            int t = dir ? (TL - 1 - s) : s;
            g_hs[((size_t)dir * TL + t) * HD + 32 * (int)crank + tid] = h;

            uint32_t off = (uint32_t)(cur * HD + 32 * (int)crank + tid) * 4u;
#pragma unroll
            for (int r = 0; r < 8; r++) st_cluster_f32(peer[r] + off, h);
        }
        cluster_sync_all();   // release DSMEM stores / acquire peers' h
        gin = ginN;
    }
}

// ---------------------------------------------------------------------------
// K3: feats[t][j] = b_out[j] + concat(h_f[t], h_b[t]) · W_out[j]
// warp per timestep; W_out staged in smem.
// ---------------------------------------------------------------------------
__global__ __launch_bounds__(256) void feats_kernel(
    const float* __restrict__ Wout, const float* __restrict__ bout)
{
    __shared__ float Ws[NT * 512];
    const int tid = threadIdx.x;
    for (int i = tid; i < NT * 512; i += 256) Ws[i] = Wout[i];
    __syncthreads();

    const int wid  = tid >> 5;
    const int lane = tid & 31;
    const int t = blockIdx.x * 8 + wid;
    if (t >= TL) return;

    float acc[NT];
#pragma unroll
    for (int j = 0; j < NT; j++) acc[j] = 0.f;

#pragma unroll
    for (int i = 0; i < 8; i++) {
        float hf = g_hs[((size_t)0 * TL + t) * HD + i * 32 + lane];
#pragma unroll
        for (int j = 0; j < NT; j++) acc[j] = fmaf(hf, Ws[j * 512 + i * 32 + lane], acc[j]);
    }
#pragma unroll
    for (int i = 0; i < 8; i++) {
        float hb = g_hs[((size_t)1 * TL + t) * HD + i * 32 + lane];
#pragma unroll
        for (int j = 0; j < NT; j++) acc[j] = fmaf(hb, Ws[j * 512 + 256 + i * 32 + lane], acc[j]);
    }
#pragma unroll
    for (int j = 0; j < NT; j++) {
#pragma unroll
        for (int off = 16; off >= 1; off >>= 1)
            acc[j] += __shfl_xor_sync(0xffffffffu, acc[j], off);
    }
    if (lane < NT) g_feats[t * NT + lane] = acc[lane] + bout[lane];
}

// ---------------------------------------------------------------------------
// K4: Viterbi decode. Single block; feats staged through smem in 256-step
// chunks; warp 0 runs the DP; backpointers as uint8 in smem; backtrack + emit.
// ---------------------------------------------------------------------------
__global__ __launch_bounds__(256) void viterbi_kernel(
    const float* __restrict__ trans, float* __restrict__ out, int out_size)
{
    __shared__ float fbuf[256 * NT];
    __shared__ uint8_t bp[TL * NT];

    const int tid = threadIdx.x;
    const int lane = tid & 31;
    const int jj = (lane < NT) ? lane : (NT - 1);

    // per-lane state (warp 0)
    float fv = (jj == TAG_START) ? 0.f : NEGV;
    float Tr[NT];
#pragma unroll
    for (int i = 0; i < NT; i++) Tr[i] = trans[jj * NT + i];   // T[j][i]

    for (int c = 0; c < TL / 256; c++) {
        for (int i = tid; i < 256 * NT; i += 256) fbuf[i] = g_feats[c * 256 * NT + i];
        __syncthreads();
        if (tid < 32) {
#pragma unroll 4
            for (int st = 0; st < 256; st++) {
                float best = -3.4e38f;
                int arg = 0;
#pragma unroll
                for (int i = 0; i < NT; i++) {
                    float fvi = __shfl_sync(0xffffffffu, fv, i);
                    float cand = fvi + Tr[i];
                    if (cand > best) { best = cand; arg = i; }
                }
                fv = best + fbuf[st * NT + jj];
                if (lane < NT) bp[(c * 256 + st) * NT + lane] = (uint8_t)arg;
            }
        }
        __syncthreads();
    }

    if (tid < 32) {
        float term = fv + trans[TAG_END * NT + jj];
        float best = -3.4e38f;
        int arg = 0;
#pragma unroll
        for (int i = 0; i < NT; i++) {
            float v = __shfl_sync(0xffffffffu, term, i);
            if (v > best) { best = v; arg = i; }
        }
        if (lane == 0) {
            int base = (out_size > TL) ? 1 : 0;
            if (base) out[0] = best;
            int tag = arg;
            for (int t = TL - 1; t >= 0; t--) {
                if (base + t < out_size) out[base + t] = (float)tag;
                tag = (int)bp[t * NT + tag];
            }
        }
    }
}

// ---------------------------------------------------------------------------
extern "C" void kernel_launch(void* const* d_in, const int* in_sizes, int n_in,
                              void* d_out, int out_size) {
    const int*   words = (const int*)  d_in[0];
    const float* embed = (const float*)d_in[1];
    const float* Wihf  = (const float*)d_in[2];
    const float* Whhf  = (const float*)d_in[3];
    const float* bihf  = (const float*)d_in[4];
    const float* bhhf  = (const float*)d_in[5];
    const float* Wihb  = (const float*)d_in[6];
    const float* Whhb  = (const float*)d_in[7];
    const float* bihb  = (const float*)d_in[8];
    const float* bhhb  = (const float*)d_in[9];
    const float* Wout  = (const float*)d_in[10];
    const float* bout  = (const float*)d_in[11];
    const float* trans = (const float*)d_in[12];
    const float* h0    = (const float*)d_in[13];
    const float* c0    = (const float*)d_in[14];
    float* out = (float*)d_out;

    gin_gemm<<<dim3(TL / 128, 8, 2), 256>>>(words, embed, Wihf, bihf, bhhf, Wihb, bihb, bhhb);
    lstm_kernel<<<16, 256>>>(Whhf, Whhb, h0, c0);
    feats_kernel<<<TL / 8, 256>>>(Wout, bout);
    viterbi_kernel<<<1, 256>>>(trans, out, out_size);
}

// round 3
// speedup vs baseline: 1.3709x; 1.3709x over previous
#include <cuda_runtime.h>
#include <cuda_bf16.h>
#include <cstdint>
#include <math.h>

#define TL 2048
#define EMB 256
#define HD 256           // per-direction hidden
#define NT 7
#define TAG_START 5
#define TAG_END 6
#define NEGV -10000.0f

// Scratch (device globals; no allocation allowed)
__device__ float g_gin[2 * TL * 1024];    // [dir][t][1024] x@Wih^T + b_ih + b_hh
__device__ float g_hs[2 * TL * HD];       // [dir][t][HD]
__device__ float g_feats[TL * NT];

// ---------------------------------------------------------------------------
// PTX helpers
// ---------------------------------------------------------------------------
__device__ __forceinline__ uint32_t smem_u32(const void* p) {
    uint32_t a;
    asm("{ .reg .u64 t; cvta.to.shared.u64 t, %1; cvt.u32.u64 %0, t; }" : "=r"(a) : "l"(p));
    return a;
}
__device__ __forceinline__ uint32_t mapa_u32(uint32_t addr, uint32_t rank) {
    uint32_t r;
    asm("mapa.shared::cluster.u32 %0, %1, %2;" : "=r"(r) : "r"(addr), "r"(rank));
    return r;
}
__device__ __forceinline__ uint32_t my_ctarank() {
    uint32_t r;
    asm("mov.u32 %0, %%cluster_ctarank;" : "=r"(r));
    return r;
}
__device__ __forceinline__ void cluster_sync_all() {
    asm volatile("barrier.cluster.arrive.aligned;" ::: "memory");
    asm volatile("barrier.cluster.wait.aligned;" ::: "memory");
}
__device__ __forceinline__ void mbar_init(uint32_t a, uint32_t n) {
    asm volatile("mbarrier.init.shared.b64 [%0], %1;" :: "r"(a), "r"(n) : "memory");
}
__device__ __forceinline__ void mbar_expect(uint32_t a, uint32_t tx) {
    asm volatile("mbarrier.arrive.expect_tx.shared.b64 _, [%0], %1;" :: "r"(a), "r"(tx) : "memory");
}
__device__ __forceinline__ void mbar_wait(uint32_t a, uint32_t phase) {
    uint32_t done;
    asm volatile(
        "{\n\t.reg .pred p;\n\t"
        "mbarrier.try_wait.parity.acquire.cluster.shared::cta.b64 p, [%1], %2;\n\t"
        "selp.b32 %0, 1, 0, p;\n\t}"
        : "=r"(done) : "r"(a), "r"(phase) : "memory");
    if (!done) {
        asm volatile(
            "{\n\t.reg .pred P;\n"
            "W%=:\n\t"
            "mbarrier.try_wait.parity.acquire.cluster.shared::cta.b64 P, [%0], %1, 0x989680;\n\t"
            "@P bra D%=;\n\t"
            "bra W%=;\n"
            "D%=:\n\t}"
            :: "r"(a), "r"(phase) : "memory");
    }
}
__device__ __forceinline__ void st_async_f32(uint32_t daddr, float v, uint32_t baddr) {
    asm volatile("st.async.shared::cluster.mbarrier::complete_tx::bytes.u32 [%0], %1, [%2];"
                 :: "r"(daddr), "r"(__float_as_uint(v)), "r"(baddr) : "memory");
}
// f32x2 packed FMA (Blackwell FFMA2; only reachable via PTX)
__device__ __forceinline__ void fma2(unsigned long long& d, unsigned long long a, unsigned long long b) {
    asm("fma.rn.f32x2 %0, %1, %2, %0;" : "+l"(d) : "l"(a), "l"(b));
}
__device__ __forceinline__ float sum2(unsigned long long v) {
    uint32_t lo, hi;
    asm("mov.b64 {%0, %1}, %2;" : "=r"(lo), "=r"(hi) : "l"(v));
    return __uint_as_float(lo) + __uint_as_float(hi);
}
// fast-but-accurate activations (EX2-based exp, 2^-21 rel err)
__device__ __forceinline__ float sig_f(float x) {
    return 1.f / (1.f + __expf(-x));
}
__device__ __forceinline__ float tanh_f(float x) {
    return 1.f - 2.f / (__expf(2.f * x) + 1.f);
}

// ---------------------------------------------------------------------------
// K1: input projection GEMM. Gin[dir][t][row] = X[t]·Wih[row] + bih[row] + bhh[row]
// ---------------------------------------------------------------------------
__global__ __launch_bounds__(256) void gin_gemm(
    const int* __restrict__ words, const float* __restrict__ embed,
    const float* __restrict__ Wf, const float* __restrict__ bif, const float* __restrict__ bhf,
    const float* __restrict__ Wb, const float* __restrict__ bib, const float* __restrict__ bhb)
{
    const int dir = blockIdx.z;
    const float* W  = dir ? Wb  : Wf;
    const float* bi = dir ? bib : bif;
    const float* bh = dir ? bhb : bhf;
    const int t0  = blockIdx.x * 128;
    const int r0  = blockIdx.y * 128;

    __shared__ float Xs[128][33];
    __shared__ float Ws[128][33];
    __shared__ int   sw[128];

    const int tid = threadIdx.x;
    const int tx = tid & 15, ty = tid >> 4;

    if (tid < 128) sw[tid] = words[t0 + tid];

    float acc[8][8];
#pragma unroll
    for (int i = 0; i < 8; i++)
#pragma unroll
        for (int j = 0; j < 8; j++) acc[i][j] = 0.f;

    for (int kb = 0; kb < EMB; kb += 32) {
        __syncthreads();
#pragma unroll
        for (int it = 0; it < 16; it++) {
            int idx = tid + it * 256;
            int r = idx >> 5, k = idx & 31;
            Xs[r][k] = embed[(size_t)sw[r] * EMB + kb + k];
        }
#pragma unroll
        for (int it = 0; it < 16; it++) {
            int idx = tid + it * 256;
            int r = idx >> 5, k = idx & 31;
            Ws[r][k] = W[(size_t)(r0 + r) * EMB + kb + k];
        }
        __syncthreads();
#pragma unroll
        for (int k = 0; k < 32; k++) {
            float xr[8], wr[8];
#pragma unroll
            for (int i = 0; i < 8; i++) xr[i] = Xs[ty + i * 16][k];
#pragma unroll
            for (int j = 0; j < 8; j++) wr[j] = Ws[tx + j * 16][k];
#pragma unroll
            for (int i = 0; i < 8; i++)
#pragma unroll
                for (int j = 0; j < 8; j++) acc[i][j] = fmaf(xr[i], wr[j], acc[i][j]);
        }
    }
#pragma unroll
    for (int j = 0; j < 8; j++) {
        int row = r0 + tx + j * 16;
        float bb = bi[row] + bh[row];
#pragma unroll
        for (int i = 0; i < 8; i++) {
            int t = t0 + ty + i * 16;
            g_gin[((size_t)dir * TL + t) * 1024 + row] = acc[i][j] + bb;
        }
    }
}

// ---------------------------------------------------------------------------
// K2: sequential BiLSTM. Two 8-CTA clusters (one per direction).
// Each CTA: 32 hidden units = 128 gate rows; Whh slice in registers as f32x2.
// h broadcast via st.async + mbarrier complete_tx, double-buffered h + 2 barriers.
// One __syncthreads per step; no cluster.sync in the loop.
// ---------------------------------------------------------------------------
__global__ __launch_bounds__(256, 1) __cluster_dims__(8, 1, 1)
void lstm_kernel(const float* __restrict__ Whf, const float* __restrict__ Whb,
                 const float* __restrict__ h0, const float* __restrict__ c0)
{
    __shared__ __align__(16) float hbuf[2 * HD];
    __shared__ float gates[128];
    __shared__ __align__(8) unsigned long long bars[2];

    const int tid = threadIdx.x;
    const int dir = blockIdx.x >> 3;
    const uint32_t crank = my_ctarank();

    const int rowl = tid >> 1;       // 0..127 : gate*32 + u
    const int half = tid & 1;        // which 128-wide half of the k range
    const int gate = rowl >> 5;      // 0..3 (uniform per warp)
    const int u0   = rowl & 31;
    const int grow = gate * 256 + 32 * (int)crank + u0;   // global gate row
    const float* Wh = dir ? Whb : Whf;

    // Whh slice -> registers: 128 floats as 64 f32x2
    unsigned long long w[64];
    {
        const unsigned long long* wp =
            (const unsigned long long*)(Wh + (size_t)grow * HD + (half << 7));
#pragma unroll
        for (int j = 0; j < 64; j++) w[j] = wp[j];
    }

    // init: h(-1) in slot 1 (prev at s=0); c0 in unit-thread registers
    hbuf[HD + tid] = h0[dir * HD + tid];
    float creg = 0.f;
    if (tid < 32) creg = c0[dir * HD + 32 * (int)crank + tid];

    const uint32_t hloc = smem_u32(hbuf);
    const uint32_t bar0 = smem_u32(&bars[0]);
    uint32_t peer_h[8], peer_b[8];
#pragma unroll
    for (int r = 0; r < 8; r++) {
        peer_h[r] = mapa_u32(hloc, (uint32_t)r);
        peer_b[r] = mapa_u32(bar0, (uint32_t)r);
    }

    if (tid == 0) {
        mbar_init(bar0, 1);
        mbar_init(bar0 + 8, 1);
        asm volatile("fence.mbarrier_init.release.cluster;" ::: "memory");
        mbar_expect(bar0, 1024);        // arm phase 0 of both barriers
        mbar_expect(bar0 + 8, 1024);
    }
    __syncthreads();
    cluster_sync_all();                 // barriers + hbuf init visible cluster-wide

    const size_t ginbase = (size_t)dir * TL * 1024 + grow;
    float gin = g_gin[ginbase + (size_t)(dir ? TL - 1 : 0) * 1024];

    for (int s = 0; s < TL; s++) {
        const int prev = (s + 1) & 1;
        const int cur  = s & 1;

        // prefetch next step's input projection (independent of the h chain)
        float ginN = 0.f;
        if (s + 1 < TL) {
            int tn = dir ? (TL - 2 - s) : (s + 1);
            ginN = g_gin[ginbase + (size_t)tn * 1024];
        }

        if (s > 0) {
            mbar_wait(bar0 + 8u * (uint32_t)prev, (uint32_t)(((s - 1) >> 1) & 1));
            if (tid == 0) mbar_expect(bar0 + 8u * (uint32_t)prev, 1024);  // re-arm next phase
        }

        // gate dot: 128 MACs/thread = 64 FFMA2, registers x smem h
        const ulonglong2* hp2 = (const ulonglong2*)(hbuf + prev * HD + (half << 7));
        unsigned long long a0 = 0ull, a1 = 0ull, a2 = 0ull, a3 = 0ull;
#pragma unroll
        for (int j = 0; j < 16; j++) {
            ulonglong2 h01 = hp2[2 * j];
            ulonglong2 h23 = hp2[2 * j + 1];
            fma2(a0, w[4 * j + 0], h01.x);
            fma2(a1, w[4 * j + 1], h01.y);
            fma2(a2, w[4 * j + 2], h23.x);
            fma2(a3, w[4 * j + 3], h23.y);
        }
        float sum = (sum2(a0) + sum2(a1)) + (sum2(a2) + sum2(a3));
        sum += __shfl_xor_sync(0xffffffffu, sum, 1);

        // fused activation + single gates write (half==0 lanes only)
        if (!half) {
            float v = sum + gin;
            gates[rowl] = (gate == 2) ? tanh_f(v) : sig_f(v);
        }
        __syncthreads();

        if (tid < 32) {
            float gi = gates[tid];
            float gf = gates[32 + tid];
            float gg = gates[64 + tid];
            float go = gates[96 + tid];
            creg = gf * creg + gi * gg;
            float h = go * tanh_f(creg);

            int t = dir ? (TL - 1 - s) : s;
            g_hs[((size_t)dir * TL + t) * HD + 32 * (int)crank + tid] = h;

            uint32_t off = (uint32_t)(cur * HD + 32 * (int)crank + tid) * 4u;
            uint32_t boff = 8u * (uint32_t)cur;
#pragma unroll
            for (int r = 0; r < 8; r++)
                st_async_f32(peer_h[r] + off, h, peer_b[r] + boff);
        }
        gin = ginN;
        // No second __syncthreads: next-step gate writes are ordered behind the
        // mbarrier wait, which requires this CTA's sends, which follow the reads.
    }
    // Drain: last writes went to bar[1] (s=2047); its 1024th completion = parity 1.
    mbar_wait(bar0 + 8, 1u);
    cluster_sync_all();
}

// ---------------------------------------------------------------------------
// K3: feats[t][j] = b_out[j] + concat(h_f[t], h_b[t]) · W_out[j]
// ---------------------------------------------------------------------------
__global__ __launch_bounds__(256) void feats_kernel(
    const float* __restrict__ Wout, const float* __restrict__ bout)
{
    __shared__ float Ws[NT * 512];
    const int tid = threadIdx.x;
    for (int i = tid; i < NT * 512; i += 256) Ws[i] = Wout[i];
    __syncthreads();

    const int wid  = tid >> 5;
    const int lane = tid & 31;
    const int t = blockIdx.x * 8 + wid;
    if (t >= TL) return;

    float acc[NT];
#pragma unroll
    for (int j = 0; j < NT; j++) acc[j] = 0.f;

#pragma unroll
    for (int i = 0; i < 8; i++) {
        float hf = g_hs[((size_t)0 * TL + t) * HD + i * 32 + lane];
#pragma unroll
        for (int j = 0; j < NT; j++) acc[j] = fmaf(hf, Ws[j * 512 + i * 32 + lane], acc[j]);
    }
#pragma unroll
    for (int i = 0; i < 8; i++) {
        float hb = g_hs[((size_t)1 * TL + t) * HD + i * 32 + lane];
#pragma unroll
        for (int j = 0; j < NT; j++) acc[j] = fmaf(hb, Ws[j * 512 + 256 + i * 32 + lane], acc[j]);
    }
#pragma unroll
    for (int j = 0; j < NT; j++) {
#pragma unroll
        for (int off = 16; off >= 1; off >>= 1)
            acc[j] += __shfl_xor_sync(0xffffffffu, acc[j], off);
    }
    if (lane < NT) g_feats[t * NT + lane] = acc[lane] + bout[lane];
}

// ---------------------------------------------------------------------------
// K4: Viterbi decode (single block; proven correct in R1)
// ---------------------------------------------------------------------------
__global__ __launch_bounds__(256) void viterbi_kernel(
    const float* __restrict__ trans, float* __restrict__ out, int out_size)
{
    __shared__ float fbuf[256 * NT];
    __shared__ uint8_t bp[TL * NT];

    const int tid = threadIdx.x;
    const int lane = tid & 31;
    const int jj = (lane < NT) ? lane : (NT - 1);

    float fv = (jj == TAG_START) ? 0.f : NEGV;
    float Tr[NT];
#pragma unroll
    for (int i = 0; i < NT; i++) Tr[i] = trans[jj * NT + i];

    for (int c = 0; c < TL / 256; c++) {
        for (int i = tid; i < 256 * NT; i += 256) fbuf[i] = g_feats[c * 256 * NT + i];
        __syncthreads();
        if (tid < 32) {
#pragma unroll 4
            for (int st = 0; st < 256; st++) {
                float best = -3.4e38f;
                int arg = 0;
#pragma unroll
                for (int i = 0; i < NT; i++) {
                    float fvi = __shfl_sync(0xffffffffu, fv, i);
                    float cand = fvi + Tr[i];
                    if (cand > best) { best = cand; arg = i; }
                }
                fv = best + fbuf[st * NT + jj];
                if (lane < NT) bp[(c * 256 + st) * NT + lane] = (uint8_t)arg;
            }
        }
        __syncthreads();
    }

    if (tid < 32) {
        float term = fv + trans[TAG_END * NT + jj];
        float best = -3.4e38f;
        int arg = 0;
#pragma unroll
        for (int i = 0; i < NT; i++) {
            float v = __shfl_sync(0xffffffffu, term, i);
            if (v > best) { best = v; arg = i; }
        }
        if (lane == 0) {
            int base = (out_size > TL) ? 1 : 0;
            if (base) out[0] = best;
            int tag = arg;
            for (int t = TL - 1; t >= 0; t--) {
                if (base + t < out_size) out[base + t] = (float)tag;
                tag = (int)bp[t * NT + tag];
            }
        }
    }
}

// ---------------------------------------------------------------------------
extern "C" void kernel_launch(void* const* d_in, const int* in_sizes, int n_in,
                              void* d_out, int out_size) {
    const int*   words = (const int*)  d_in[0];
    const float* embed = (const float*)d_in[1];
    const float* Wihf  = (const float*)d_in[2];
    const float* Whhf  = (const float*)d_in[3];
    const float* bihf  = (const float*)d_in[4];
    const float* bhhf  = (const float*)d_in[5];
    const float* Wihb  = (const float*)d_in[6];
    const float* Whhb  = (const float*)d_in[7];
    const float* bihb  = (const float*)d_in[8];
    const float* bhhb  = (const float*)d_in[9];
    const float* Wout  = (const float*)d_in[10];
    const float* bout  = (const float*)d_in[11];
    const float* trans = (const float*)d_in[12];
    const float* h0    = (const float*)d_in[13];
    const float* c0    = (const float*)d_in[14];
    float* out = (float*)d_out;

    gin_gemm<<<dim3(TL / 128, 8, 2), 256>>>(words, embed, Wihf, bihf, bhhf, Wihb, bihb, bhhb);
    lstm_kernel<<<16, 256>>>(Whhf, Whhb, h0, c0);
    feats_kernel<<<TL / 8, 256>>>(Wout, bout);
    viterbi_kernel<<<1, 256>>>(trans, out, out_size);
}